// round 7
// baseline (speedup 1.0000x reference)
#include <cuda_runtime.h>
#include <math.h>
#include <math_constants.h>

#define H 128
#define HP (H + 1)
#define NSEG 129
#define NPIECE 129
#define THRESH 0.045f
#define INV_TAU 0.05f
#define THR 1024
#define NWARP (THR / 32)
#define NCMAX (NSEG * H + (NSEG - 1))   // 16640
#define NPMAX (NCMAX + 1)               // 16641
#define NB 8192
#define XLO (-8.0f)
#define BINSCALE 512.0f
#define SETUPB 129                       // setup block id (grid is 147 here)

// -------- device scratch (no cudaMalloc) --------
__device__ float  g_bp[H];
__device__ float  g_cut[NSEG * H];
__device__ float2 g_AB[NSEG * NPIECE];
__device__ int    g_cnt[NSEG];
__device__ __align__(16) float  g_cutC[NCMAX];
__device__ __align__(16) float2 g_ABC[NPMAX];
__device__ unsigned short g_bin[NB + 1];
__device__ int    g_meta[4];
__device__ unsigned long long g_sync[256];
__device__ unsigned g_barrier;          // modular counter: multiple of grid at launch edges
__device__ volatile unsigned g_flag;    // setup-done flag (zeroed pre-barrier by SETUPB)

// grid-wide barrier: all blocks co-resident (grid <= #SMs, 1 CTA/SM)
__device__ __forceinline__ void grid_barrier(unsigned grid) {
    __threadfence();
    __syncthreads();
    if (threadIdx.x == 0) {
        __threadfence();
        unsigned tk = atomicAdd(&g_barrier, 1u) + 1u;
        if (tk % grid != 0u) {
            while (*((volatile unsigned*)&g_barrier) % grid != 0u) { }
        }
        __threadfence();
    }
    __syncthreads();
}

template <int IT>
__global__ void __launch_bounds__(THR, 1)
k_all(const float* __restrict__ x,
      const float* __restrict__ W1, const float* __restrict__ B1,
      const float* __restrict__ W2, const float* __restrict__ B2,
      const float* __restrict__ W3, const float* __restrict__ B3,
      float* __restrict__ out, int N, int out_size) {
    extern __shared__ char dyn[];
    int t = threadIdx.x, b = blockIdx.x;
    int lane = t & 31, w = t >> 5;
    unsigned grid = gridDim.x;

    __shared__ int   stot[NWARP * 16];
    __shared__ int   swarp[NWARP];
    __shared__ unsigned ssum[NWARP];
    __shared__ float redA[4], redB[4];
    __shared__ int   scw[4];
    __shared__ int   soff[NSEG + 1];
    __shared__ int   sBlockLast, sSeedSh, sCntOwn, sNC;

    // ---- zero own lookback slot (+ flag) BEFORE barrier ----
    if (t == 0) {
        g_sync[b] = 0ull;
        if (b == SETUPB || (grid <= SETUPB && b == grid - 1)) g_flag = 0u;
    }

    // =========================== BUILD ===========================
    {
        // dynamic smem build layout
        float* sW2  = (float*)dyn;                    // H*HP
        float* pA   = sW2 + H * HP;                   // 8*H
        float* pB   = pA + 8 * H;
        float* pSA  = pB + 8 * H;
        float* pSB  = pSA + 8 * H;
        int*   pPre = (int*)(pSB + 8 * H);            // 8*H
        float* sw1  = (float*)(pPre + 8 * H);
        float* sb1  = sw1 + H;
        float* sbp  = sb1 + H;
        float* sbpS = sbp + H;
        float* swm  = sbpS + H;
        float* sbm  = swm + H;
        float* skey = sbm + H;
        float* sdA  = skey + H;
        float* sdB  = sdA + H;

        if (b < NSEG) {
            int j = t & 127, q = t >> 7;              // 8 groups of 16
            // coalesced W2 -> padded smem
            const float4* w4 = (const float4*)W2;
            #pragma unroll
            for (int i = t; i < (H * H) / 4; i += THR) {
                float4 v = w4[i];
                int base = i << 2;
                int row = base >> 7, col = base & 127;
                float* dst = sW2 + row * HP + col;
                dst[0] = v.x; dst[1] = v.y; dst[2] = v.z; dst[3] = v.w;
            }
            if (q == 0) {
                float wj = W1[j], bj = B1[j];
                sw1[j] = wj; sb1[j] = bj;
                sbp[j] = (wj == 0.0f) ? CUDART_INF_F : (-bj / wj);
            }
            __syncthreads();

            for (int s = b; s < NSEG; s += grid) {
                // breakpoint rank, 8-way
                float bpj = sbp[j];
                {
                    int r = 0;
                    #pragma unroll 8
                    for (int k = q * 16; k < q * 16 + 16; k++) {
                        float v = sbp[k];
                        r += (v < bpj) || (v == bpj && k < j);
                    }
                    pPre[q * H + j] = r;
                }
                __syncthreads();
                if (q == 0) {
                    int rank = 0;
                    #pragma unroll
                    for (int g = 0; g < 8; g++) rank += pPre[g * H + j];
                    sbpS[rank] = bpj;
                    if (s == 0) g_bp[rank] = bpj;
                }
                __syncthreads();
                float L = (s == 0)        ? -CUDART_INF_F : sbpS[s - 1];
                float R = (s == NSEG - 1) ?  CUDART_INF_F : sbpS[s];
                if (q == 0) {
                    float wj = sw1[j], bj = sb1[j];
                    bool act;
                    if (wj > 0.0f)      act = (sbp[j] <= L);
                    else if (wj < 0.0f) act = (sbp[j] >= R);
                    else                act = (bj > 0.0f);
                    swm[j] = act ? wj : 0.0f;
                    sbm[j] = act ? bj : 0.0f;
                }
                __syncthreads();
                // matvec partials, 8-way over m
                {
                    float a = 0.0f, be = 0.0f;
                    const float* row = sW2 + j * HP;
                    #pragma unroll 8
                    for (int m = q * 16; m < q * 16 + 16; m++) {
                        float c = row[m];
                        a  = fmaf(c, swm[m], a);
                        be = fmaf(c, sbm[m], be);
                    }
                    pA[q * H + j] = a; pB[q * H + j] = be;
                }
                __syncthreads();
                if (q == 0) {
                    float a = 0.0f, be = __ldg(&B2[j]);
                    #pragma unroll
                    for (int g = 0; g < 8; g++) { a += pA[g * H + j]; be += pB[g * H + j]; }
                    float w3 = __ldg(&W3[j]);
                    float c = -be / a;
                    bool hasbp = (a != 0.0f) && (c > L) && (c < R);
                    bool actL;
                    if (a > 0.0f)      actL = (c <= L);
                    else if (a < 0.0f) actL = (c > L);
                    else               actL = (be > 0.0f);
                    float eA = actL ? w3 * a  : 0.0f;
                    float eB = actL ? w3 * be : 0.0f;
                    float sgn = (a > 0.0f) ? 1.0f : -1.0f;
                    skey[j] = hasbp ? c : CUDART_INF_F;
                    sdA[j]  = hasbp ? sgn * w3 * a  : 0.0f;
                    sdB[j]  = hasbp ? sgn * w3 * be : 0.0f;
                    #pragma unroll
                    for (int o = 16; o; o >>= 1) {
                        eA += __shfl_xor_sync(0xffffffffu, eA, o);
                        eB += __shfl_xor_sync(0xffffffffu, eB, o);
                    }
                    unsigned bal = __ballot_sync(0xffffffffu, hasbp);
                    if (lane == 0) { redA[w] = eA; redB[w] = eB; scw[w] = __popc(bal); }
                }
                __syncthreads();
                if (t == 0) g_cnt[s] = scw[0] + scw[1] + scw[2] + scw[3];
                // fused rank + prefix over sorted cuts, 8-way
                {
                    float key = skey[j];
                    int pre = 0;
                    float sA = 0.0f, sB = 0.0f;
                    #pragma unroll 8
                    for (int k = q * 16; k < q * 16 + 16; k++) {
                        float kk = skey[k];
                        bool p = (kk < key) || (kk == key && k <= j);
                        if (p) { sA += sdA[k]; sB += sdB[k]; pre++; }
                    }
                    pPre[q * H + j] = pre; pSA[q * H + j] = sA; pSB[q * H + j] = sB;
                }
                __syncthreads();
                if (q == 0) {
                    float A0 = redA[0] + redA[1] + redA[2] + redA[3];
                    float B0 = redB[0] + redB[1] + redB[2] + redB[3] + __ldg(&B3[0]);
                    int pre = 0; float sA = 0.0f, sB = 0.0f;
                    #pragma unroll
                    for (int g = 0; g < 8; g++) {
                        pre += pPre[g * H + j]; sA += pSA[g * H + j]; sB += pSB[g * H + j];
                    }
                    int rank = pre - 1;
                    g_cut[s * H + rank] = skey[j];
                    g_AB[s * NPIECE + 1 + rank] = make_float2(A0 + sA, B0 + sB);
                    if (j == 0) g_AB[s * NPIECE] = make_float2(A0, B0);
                }
                __syncthreads();
            }
        }
    }

    // =========== GRID BARRIER (build + slot-zero visible) ===========
    grid_barrier(grid);

    // =========================== SCAN ===========================
    long blockBase = (long)b * THR * IT;
    float xr[IT];
    int   vloc[IT];
    int   rr[IT];
    int cntLoc = 0;
    #pragma unroll
    for (int tile = 0; tile < IT; tile++) {
        long row = blockBase + (long)tile * THR + t;
        bool valid = row < N;
        float cur = valid ? __ldg(x + row) : 0.0f;
        float pv = __shfl_up_sync(0xffffffffu, cur, 1);
        if (lane == 0) pv = (valid && row > 0) ? __ldg(x + row - 1) : cur;
        bool m = valid && ((row == 0) || fabsf(cur - pv) > THRESH);
        cntLoc += m ? 1 : 0;
        int v = m ? (int)row : -1;
        #pragma unroll
        for (int o = 1; o < 32; o <<= 1) {
            int u = __shfl_up_sync(0xffffffffu, v, o);
            if (lane >= o) v = max(v, u);
        }
        vloc[tile] = v;
        xr[tile] = cur;
        if (lane == 31) stot[tile * NWARP + w] = v;
    }
    __syncthreads();
    if (w == 0) {
        // exclusive prefix max over flat offsets == (tile,warp)-lex order
        int vals[IT];
        int running = -1;
        #pragma unroll
        for (int i = 0; i < IT; i++) {
            int u = stot[lane * IT + i];
            vals[i] = running;
            running = max(running, u);
        }
        int inc = running;
        #pragma unroll
        for (int o = 1; o < 32; o <<= 1) {
            int u = __shfl_up_sync(0xffffffffu, inc, o);
            if (lane >= o) inc = max(inc, u);
        }
        int exc = __shfl_up_sync(0xffffffffu, inc, 1);
        if (lane == 0) exc = -1;
        #pragma unroll
        for (int i = 0; i < IT; i++) stot[lane * IT + i] = max(vals[i], exc);
        if (lane == 31) sBlockLast = inc;
    }
    __syncthreads();
    #pragma unroll
    for (int tile = 0; tile < IT; tile++)
        rr[tile] = max(vloc[tile], stot[tile * NWARP + w]);
    int carry = sBlockLast;

    // ---- publish packet ----
    {
        int c = cntLoc;
        #pragma unroll
        for (int o = 16; o; o >>= 1) c += __shfl_xor_sync(0xffffffffu, c, o);
        if (lane == 0) swarp[w] = c;
        __syncthreads();
        if (t == 0) {
            int s = 0;
            #pragma unroll
            for (int i = 0; i < NWARP; i++) s += swarp[i];
            sCntOwn = s;
            unsigned long long pack =
                ((unsigned long long)(unsigned)(carry + 2) << 32) | (unsigned)s;
            atomicExch(&g_sync[b], pack);
        }
        __syncthreads();
    }

    // =========================== SETUP (one block) ===========================
    bool iam_setup = (grid > SETUPB) ? (b == SETUPB) : (b == grid - 1);
    if (iam_setup) {
        int* cnt8 = (int*)dyn;                   // NB ints
        for (int i = t; i < NB; i += THR) cnt8[i] = 0;
        __syncthreads();
        if (t == 0) {
            int o = 0;
            #pragma unroll 4
            for (int s = 0; s < NSEG; s++) { soff[s] = o; o += g_cnt[s] + 1; }
            soff[NSEG] = o;
            sNC = o - 1;
            g_meta[0] = o - 1;
        }
        __syncthreads();
        int NC = sNC, NP = NC + 1;
        for (int p = t; p < NP; p += THR) {
            int lo = 0, hi = NSEG;
            while (lo + 1 < hi) {
                int mid = (lo + hi) >> 1;
                if (soff[mid] <= p) lo = mid; else hi = mid;
            }
            int s = lo;
            int k = p - soff[s];
            int cnt = soff[s + 1] - soff[s] - 1;
            g_ABC[p] = g_AB[s * NPIECE + k];
            if (p < NC) {
                float cv = (k < cnt) ? g_cut[s * H + k] : g_bp[s];
                g_cutC[p] = cv;
                int bin = (int)((cv - XLO) * BINSCALE);
                bin = min(max(bin, 0), NB - 1);
                atomicAdd(&cnt8[bin], 1);
            }
        }
        __syncthreads();
        const int PER = NB / THR;   // 8
        int base = t * PER;
        int loc[PER];
        int tsum = 0;
        #pragma unroll
        for (int i = 0; i < PER; i++) { loc[i] = cnt8[base + i]; tsum += loc[i]; }
        int inc = tsum;
        #pragma unroll
        for (int o = 1; o < 32; o <<= 1) {
            int u = __shfl_up_sync(0xffffffffu, inc, o);
            if (lane >= o) inc += u;
        }
        if (lane == 31) swarp[w] = inc;
        __syncthreads();
        if (w == 0) {
            int z = swarp[lane];
            #pragma unroll
            for (int o = 1; o < 32; o <<= 1) {
                int u = __shfl_up_sync(0xffffffffu, z, o);
                if (lane >= o) z += u;
            }
            swarp[lane] = z;
        }
        __syncthreads();
        int excl = inc - tsum + ((w > 0) ? swarp[w - 1] : 0);
        #pragma unroll
        for (int i = 0; i < PER; i++) {
            g_bin[base + i] = (unsigned short)excl;
            excl += loc[i];
        }
        if (t == THR - 1) g_bin[NB] = (unsigned short)excl;
        __threadfence();
        __syncthreads();
        if (t == 0) g_flag = 1u;
    }

    // =========================== LOOKBACK ===========================
    {
        int lastMax = -1;
        unsigned sumU = 0;
        for (int i = t; i < b; i += THR) {
            volatile unsigned long long* p = (volatile unsigned long long*)(g_sync + i);
            unsigned long long v;
            do { v = *p; } while (v == 0ull);
            lastMax = max(lastMax, (int)(unsigned)(v >> 32) - 2);
            sumU += (unsigned)(v & 0xffffffffull);
        }
        #pragma unroll
        for (int o = 16; o; o >>= 1) {
            lastMax = max(lastMax, __shfl_xor_sync(0xffffffffu, lastMax, o));
            sumU += __shfl_xor_sync(0xffffffffu, sumU, o);
        }
        if (lane == 0) { swarp[w] = lastMax; ssum[w] = sumU; }
        __syncthreads();
        if (t == 0) {
            int mx = -1; unsigned s2 = 0;
            #pragma unroll
            for (int i = 0; i < NWARP; i++) { mx = max(mx, swarp[i]); s2 += ssum[i]; }
            sSeedSh = mx;
            if (b == grid - 1 && out_size > N)
                out[N] = (float)(s2 + (unsigned)sCntOwn);
        }
        if (b == 0)
            for (int i = N + 1 + t; i < out_size; i += THR) out[i] = 0.0f;
    }

    // ---- wait for setup, then load tables ----
    if (t == 0) { while (g_flag == 0u) { } }
    __syncthreads();
    __threadfence();

    float*  scut = (float*)dyn;
    float2* sAB  = (float2*)(dyn + NCMAX * sizeof(float));
    unsigned short* sbin =
        (unsigned short*)(dyn + NCMAX * sizeof(float) + NPMAX * sizeof(float2));
    {
        int NC = g_meta[0];
        int NP = NC + 1;
        const float4* c4 = (const float4*)g_cutC;
        float4* e4 = (float4*)scut;
        int m4 = NC >> 2;
        for (int i = t; i < m4; i += THR) e4[i] = c4[i];
        for (int i = (m4 << 2) + t; i < NC; i += THR) scut[i] = g_cutC[i];
        const float4* s4 = (const float4*)g_ABC;
        float4* d4 = (float4*)sAB;
        int n4 = (NP * 2) >> 2;
        for (int i = t; i < n4; i += THR) d4[i] = s4[i];
        for (int i = (n4 << 2) + t; i < NP * 2; i += THR)
            ((float*)sAB)[i] = ((const float*)g_ABC)[i];
        for (int i = t; i <= NB; i += THR) sbin[i] = g_bin[i];
    }
    __syncthreads();
    int seed = sSeedSh;

    // =========================== EVAL ===========================
    #pragma unroll
    for (int tile = 0; tile < IT; tile++) {
        long row = blockBase + (long)tile * THR + t;
        if (row >= N) break;
        int irow = (int)row;
        int run = max(rr[tile], seed);
        float xv = (run == irow) ? xr[tile] : __ldg(x + run);
        int bin = (int)((xv - XLO) * BINSCALE);
        bin = min(max(bin, 0), NB - 1);
        int lo = sbin[bin], hi = sbin[bin + 1];
        while (lo < hi) {
            int mid = (lo + hi) >> 1;
            if (scut[mid] < xv) lo = mid + 1; else hi = mid;
        }
        float2 ab = sAB[lo];
        float y = fmaf(ab.x, xv, ab.y);
        out[row] = (run == irow) ? y : y * __expf((float)(run - irow) * INV_TAU);
    }
}

#define LAUNCH_ALL(ITV)                                                          \
    do {                                                                         \
        cudaFuncSetAttribute(k_all<ITV>,                                         \
            cudaFuncAttributeMaxDynamicSharedMemorySize, (int)smemB);            \
        k_all<ITV><<<grid1, THR, smemB>>>(x, W1, b1, W2, b2, W3, b3,             \
                                          out, N, out_size);                     \
    } while (0)

extern "C" void kernel_launch(void* const* d_in, const int* in_sizes, int n_in,
                              void* d_out, int out_size) {
    const float* x  = (const float*)d_in[0];
    const float* W1 = (const float*)d_in[1];
    const float* b1 = (const float*)d_in[2];
    const float* W2 = (const float*)d_in[3];
    const float* b2 = (const float*)d_in[4];
    const float* W3 = (const float*)d_in[5];
    const float* b3 = (const float*)d_in[6];
    float* out = (float*)d_out;
    int N = in_sizes[0];

    const int SMS = 147;   // <= 148 active SMs: guarantees co-residency @ 1 CTA/SM
    long total = N;
    int IT = (int)((total + (long)SMS * THR - 1) / ((long)SMS * THR));
    if (IT < 1) IT = 1;
    if (IT > 16) IT = 16;
    int grid1 = (int)((total + (long)THR * IT - 1) / ((long)THR * IT));
    if (grid1 < 1) grid1 = 1;

    size_t smemB = (size_t)NCMAX * sizeof(float) + (size_t)NPMAX * sizeof(float2)
                 + (size_t)(NB + 1) * sizeof(unsigned short) + 16;

    switch (IT) {
        case 1:  LAUNCH_ALL(1);  break;
        case 2:  LAUNCH_ALL(2);  break;
        case 3:  LAUNCH_ALL(3);  break;
        case 4:  LAUNCH_ALL(4);  break;
        case 5:  LAUNCH_ALL(5);  break;
        case 6:  LAUNCH_ALL(6);  break;
        case 7:  LAUNCH_ALL(7);  break;
        case 8:  LAUNCH_ALL(8);  break;
        case 9:  LAUNCH_ALL(9);  break;
        case 10: LAUNCH_ALL(10); break;
        case 11: LAUNCH_ALL(11); break;
        case 12: LAUNCH_ALL(12); break;
        case 13: LAUNCH_ALL(13); break;
        case 14: LAUNCH_ALL(14); break;
        case 15: LAUNCH_ALL(15); break;
        default: LAUNCH_ALL(16); break;
    }
}